// round 6
// baseline (speedup 1.0000x reference)
#include <cuda_runtime.h>

// Problem constants (fixed by the dataset shapes)
#define B_   32
#define NL_  13
#define L_   1024
#define D_   768
#define NBLK_ 1184   // 148 SMs * 8 blocks/SM -> exactly one full wave

// Scratch (no allocation allowed): per-(batch,pos) weights + per-batch lengths.
__device__ float g_w[B_ * L_];
__device__ int   g_len[B_];

// ---------------------------------------------------------------------------
// Kernel 1: per-batch run-length weights + zero the output + publish lengths.
// One block per batch, L_ threads. Warp-shuffle scan (2 barriers for the scan).
//
// Integer inputs are read through an int32 view with runtime-detected element
// stride (JAX silently downcasts int64->int32 without x64). lengths are in
// [512,1024] (never 0), so word[1]==0  <=>  little-endian int64 layout.
// vq values < 320 < 2^31, so low words fully determine equality either way.
// ---------------------------------------------------------------------------
__global__ void __launch_bounds__(L_, 1)
vq_weights_kernel(const int* __restrict__ len32,
                  const int* __restrict__ vq32,
                  float* __restrict__ out)
{
    const int b    = blockIdx.x;
    const int i    = threadIdx.x;
    const int lane = i & 31;
    const int warp = i >> 5;

    __shared__ int s_rl[L_];        // run length per segment id
    __shared__ int s_v0[L_];        // staged vq low words (component 0)
    __shared__ int s_v1[L_];        // staged vq low words (component 1)
    __shared__ int s_wsum[32];      // per-warp scan totals

    // Zero the output slice for this batch (d_out is poisoned to 0xAA).
    if (i < D_) out[b * D_ + i] = 0.0f;

    // dtype detection (uniform)
    const int stride = (len32[1] == 0) ? 2 : 1;

    const int  len   = len32[b * stride];
    const bool valid = i < len;
    if (i == 0) g_len[b] = len;

    const int ebase = (b * L_ + i) * 2;
    int v0 = vq32[(ebase + 0) * stride];
    int v1 = vq32[(ebase + 1) * stride];
    s_v0[i] = v0;
    s_v1[i] = v1;
    s_rl[i] = 0;
    __syncthreads();

    // boundary flag
    bool bnd;
    if (i == 0) bnd = valid;
    else        bnd = valid && (v0 != s_v0[i - 1] || v1 != s_v1[i - 1]);

    // warp-level inclusive scan of flags
    int scan = bnd ? 1 : 0;
    #pragma unroll
    for (int off = 1; off < 32; off <<= 1) {
        int n = __shfl_up_sync(0xffffffffu, scan, off);
        if (lane >= off) scan += n;
    }
    if (lane == 31) s_wsum[warp] = scan;
    __syncthreads();

    if (warp == 0) {
        int v = s_wsum[lane];
        #pragma unroll
        for (int off = 1; off < 32; off <<= 1) {
            int n = __shfl_up_sync(0xffffffffu, v, off);
            if (lane >= off) v += n;
        }
        s_wsum[lane] = v;
    }
    __syncthreads();

    const int incl  = scan + (warp > 0 ? s_wsum[warp - 1] : 0);  // inclusive cumsum
    const int total = s_wsum[31];                                 // num_runs

    int seg = incl - 1;
    seg = max(0, min(seg, L_ - 1));

    if (valid) atomicAdd(&s_rl[seg], 1);
    __syncthreads();

    float wv = 0.0f;
    if (valid) {
        float rl = (float)max(s_rl[seg], 1);
        wv = 1.0f / ((float)total * rl);
    }
    g_w[b * L_ + i] = wv;
}

// ---------------------------------------------------------------------------
// Kernel 2: weighted pool over the LAST layer of input_feature.
// Flat, globally-balanced grid: NBLK_=1184 blocks (exactly 8/SM, one wave),
// 192 threads (one float4 column group per thread, 192*4 = 768 = D).
// Block i handles global valid-row range [i*T/NBLK, (i+1)*T/NBLK) where
// T = sum(len_b): every block does 20-21 rows regardless of batch lengths.
// Batch mapping via in-block 32-entry prefix sum of g_len (warp scan).
// Loads batched 8-deep (independent LDG.128, __ldcs streaming) for MLP ~8.
// ---------------------------------------------------------------------------
__global__ void __launch_bounds__(D_ / 4, 8)
vq_pool_kernel(const float* __restrict__ feat, float* __restrict__ out)
{
    const int t = threadIdx.x;      // 0..191

    __shared__ int s_pref[B_ + 1];  // prefix sums of lengths

    if (t < 32) {
        int v = g_len[t];
        int p = v;
        #pragma unroll
        for (int off = 1; off < 32; off <<= 1) {
            int n = __shfl_up_sync(0xffffffffu, p, off);
            if (t >= off) p += n;
        }
        s_pref[t + 1] = p;          // inclusive
        if (t == 0) s_pref[0] = 0;
    }
    __syncthreads();

    const int T  = s_pref[B_];
    const int g0 = (int)(((long long)blockIdx.x       * T) / NBLK_);
    const int g1 = (int)(((long long)(blockIdx.x + 1) * T) / NBLK_);
    if (g0 >= g1) return;

    // locate batch containing g0 (uniform across block; <=32 iters)
    int b = 0;
    while (s_pref[b + 1] <= g0) ++b;

    int g = g0;
    while (g < g1) {
        const int bend = min(g1, s_pref[b + 1]);
        const int row0 = g - s_pref[b];          // first valid row in batch b
        const int nrow = bend - g;

        const float4* __restrict__ fb = (const float4*)
            (feat + ((size_t)b * NL_ + (NL_ - 1)) * (size_t)(L_ * D_));
        const float* __restrict__ wb = g_w + b * L_;

        float4 acc = make_float4(0.f, 0.f, 0.f, 0.f);

        int l = row0;
        const int lend = row0 + nrow;
        // main: 8-row batches of independent loads
        for (; l + 8 <= lend; l += 8) {
            float  wl[8];
            float4 f[8];
            #pragma unroll
            for (int k = 0; k < 8; ++k) wl[k] = wb[l + k];
            #pragma unroll
            for (int k = 0; k < 8; ++k)
                f[k] = __ldcs(&fb[(size_t)(l + k) * (D_ / 4) + t]);
            #pragma unroll
            for (int k = 0; k < 8; ++k) {
                acc.x = fmaf(wl[k], f[k].x, acc.x);
                acc.y = fmaf(wl[k], f[k].y, acc.y);
                acc.z = fmaf(wl[k], f[k].z, acc.z);
                acc.w = fmaf(wl[k], f[k].w, acc.w);
            }
        }
        // remainder (0..7 rows)
        for (; l < lend; ++l) {
            const float wl = wb[l];
            float4 f = __ldcs(&fb[(size_t)l * (D_ / 4) + t]);
            acc.x = fmaf(wl, f.x, acc.x);
            acc.y = fmaf(wl, f.y, acc.y);
            acc.z = fmaf(wl, f.z, acc.z);
            acc.w = fmaf(wl, f.w, acc.w);
        }

        float* ob = out + b * D_ + t * 4;
        atomicAdd(ob + 0, acc.x);
        atomicAdd(ob + 1, acc.y);
        atomicAdd(ob + 2, acc.z);
        atomicAdd(ob + 3, acc.w);

        g = bend;
        ++b;
    }
}

// ---------------------------------------------------------------------------
extern "C" void kernel_launch(void* const* d_in, const int* in_sizes, int n_in,
                              void* d_out, int out_size)
{
    const float* feat  = (const float*)d_in[0];   // (B, NL, L, D) f32
    const int*   len32 = (const int*)d_in[1];     // (B,) i32 or i64 (detected)
    const int*   vq32  = (const int*)d_in[2];     // (B, L, 2) i32 or i64 (detected)
    float*       out   = (float*)d_out;           // (B, D) f32

    vq_weights_kernel<<<B_, L_>>>(len32, vq32, out);

    vq_pool_kernel<<<NBLK_, D_ / 4>>>(feat, out);
}

// round 7
// speedup vs baseline: 1.3434x; 1.3434x over previous
#include <cuda_runtime.h>

// Problem constants (fixed by the dataset shapes)
#define B_   32
#define NL_  13
#define L_   1024
#define D_   768
#define LCHUNKS_ 32
#define LCHUNK_  (L_ / LCHUNKS_)   // 32 rows per block

// Scratch (no allocation allowed): per-(batch,pos) weights + per-batch lengths.
__device__ float g_w[B_ * L_];
__device__ int   g_len[B_];

// ---------------------------------------------------------------------------
// Kernel 1: per-batch run-length weights + zero the output + publish lengths.
// One block per batch, L_ threads. Warp-shuffle scan (2 barriers for the scan).
//
// Integer inputs are read through an int32 view with runtime-detected element
// stride (JAX silently downcasts int64->int32 without x64). lengths are in
// [512,1024] (never 0), so word[1]==0  <=>  little-endian int64 layout.
// vq values < 320 < 2^31, so low words fully determine equality either way.
// ---------------------------------------------------------------------------
__global__ void __launch_bounds__(L_, 1)
vq_weights_kernel(const int* __restrict__ len32,
                  const int* __restrict__ vq32,
                  float* __restrict__ out)
{
    const int b    = blockIdx.x;
    const int i    = threadIdx.x;
    const int lane = i & 31;
    const int warp = i >> 5;

    __shared__ int s_rl[L_];        // run length per segment id
    __shared__ int s_v0[L_];        // staged vq low words (component 0)
    __shared__ int s_v1[L_];        // staged vq low words (component 1)
    __shared__ int s_wsum[32];      // per-warp scan totals

    // Zero the output slice for this batch (d_out is poisoned to 0xAA).
    if (i < D_) out[b * D_ + i] = 0.0f;

    // dtype detection (uniform)
    const int stride = (len32[1] == 0) ? 2 : 1;

    const int  len   = len32[b * stride];
    const bool valid = i < len;
    if (i == 0) g_len[b] = len;

    const int ebase = (b * L_ + i) * 2;
    int v0 = vq32[(ebase + 0) * stride];
    int v1 = vq32[(ebase + 1) * stride];
    s_v0[i] = v0;
    s_v1[i] = v1;
    s_rl[i] = 0;
    __syncthreads();

    // boundary flag
    bool bnd;
    if (i == 0) bnd = valid;
    else        bnd = valid && (v0 != s_v0[i - 1] || v1 != s_v1[i - 1]);

    // warp-level inclusive scan of flags
    int scan = bnd ? 1 : 0;
    #pragma unroll
    for (int off = 1; off < 32; off <<= 1) {
        int n = __shfl_up_sync(0xffffffffu, scan, off);
        if (lane >= off) scan += n;
    }
    if (lane == 31) s_wsum[warp] = scan;
    __syncthreads();

    if (warp == 0) {
        int v = s_wsum[lane];
        #pragma unroll
        for (int off = 1; off < 32; off <<= 1) {
            int n = __shfl_up_sync(0xffffffffu, v, off);
            if (lane >= off) v += n;
        }
        s_wsum[lane] = v;
    }
    __syncthreads();

    const int incl  = scan + (warp > 0 ? s_wsum[warp - 1] : 0);  // inclusive cumsum
    const int total = s_wsum[31];                                 // num_runs

    int seg = incl - 1;
    seg = max(0, min(seg, L_ - 1));

    if (valid) atomicAdd(&s_rl[seg], 1);
    __syncthreads();

    float wv = 0.0f;
    if (valid) {
        float rl = (float)max(s_rl[seg], 1);
        wv = 1.0f / ((float)total * rl);
    }
    g_w[b * L_ + i] = wv;
}

// ---------------------------------------------------------------------------
// Kernel 2: weighted pool over the LAST layer of input_feature.
// grid = (LCHUNKS_=32, B_=32) = 1024 blocks (single wave at 8 blocks/SM),
// 192 threads (one float4 column group per thread, 192*4 = 768 = D).
// Static fully-unrolled 32-row chunk per block (R3 structure, best known).
// Blocks fully past the valid length exit; boundary chunk relies on w=0.
// Epilogue: ONE red.global.v4.f32.add per thread instead of 4 scalar
// atomicAdds -> 4x fewer L2 atomic ops (sm_90+ vectorized reduction).
// ---------------------------------------------------------------------------
__global__ void __launch_bounds__(D_ / 4, 8)
vq_pool_kernel(const float* __restrict__ feat, float* __restrict__ out)
{
    const int b  = blockIdx.y;
    const int lc = blockIdx.x;
    const int t  = threadIdx.x;     // 0..191

    const int l0 = lc * LCHUNK_;
    if (l0 >= g_len[b]) return;     // whole chunk is zero-weight

    const float4* __restrict__ fb = (const float4*)
        (feat + ((size_t)b * NL_ + (NL_ - 1)) * (size_t)(L_ * D_));
    const float* __restrict__ wb = g_w + b * L_;

    float4 acc = make_float4(0.f, 0.f, 0.f, 0.f);

    #pragma unroll
    for (int j = 0; j < LCHUNK_; j += 8) {
        float  wl[8];
        float4 f[8];
        #pragma unroll
        for (int k = 0; k < 8; ++k) wl[k] = wb[l0 + j + k];
        #pragma unroll
        for (int k = 0; k < 8; ++k)
            f[k] = __ldcs(&fb[(size_t)(l0 + j + k) * (D_ / 4) + t]);
        #pragma unroll
        for (int k = 0; k < 8; ++k) {
            acc.x = fmaf(wl[k], f[k].x, acc.x);
            acc.y = fmaf(wl[k], f[k].y, acc.y);
            acc.z = fmaf(wl[k], f[k].z, acc.z);
            acc.w = fmaf(wl[k], f[k].w, acc.w);
        }
    }

    // Single vectorized reduction (16B-aligned: t*16 bytes into a 16B-aligned row)
    float* ob = out + b * D_ + t * 4;
    asm volatile("red.global.add.v4.f32 [%0], {%1, %2, %3, %4};"
                 :: "l"(ob), "f"(acc.x), "f"(acc.y), "f"(acc.z), "f"(acc.w)
                 : "memory");
}

// ---------------------------------------------------------------------------
extern "C" void kernel_launch(void* const* d_in, const int* in_sizes, int n_in,
                              void* d_out, int out_size)
{
    const float* feat  = (const float*)d_in[0];   // (B, NL, L, D) f32
    const int*   len32 = (const int*)d_in[1];     // (B,) i32 or i64 (detected)
    const int*   vq32  = (const int*)d_in[2];     // (B, L, 2) i32 or i64 (detected)
    float*       out   = (float*)d_out;           // (B, D) f32

    vq_weights_kernel<<<B_, L_>>>(len32, vq32, out);

    dim3 grid(LCHUNKS_, B_);
    vq_pool_kernel<<<grid, D_ / 4>>>(feat, out);
}